// round 3
// baseline (speedup 1.0000x reference)
#include <cuda_runtime.h>
#include <cstdint>

#define T_LEN 4096
#define CCH   256
#define BATCH 2

// ---------------- scratch (device globals; no allocation allowed) ----------
__device__ float g_xn [BATCH * CCH * T_LEN];          // normalized input [B,C,T]
__device__ float g_qkv[BATCH * 3 * CCH * T_LEN];      // qkv [B,3C,T]
__device__ float g_att[BATCH * CCH * T_LEN];          // attention out [B,C,T]

// ---------------- GroupNorm (32 groups of 8 channels, over C/G x T) --------
__global__ void gn_kernel(const float* __restrict__ x,
                          const float* __restrict__ w,
                          const float* __restrict__ bb) {
    int b = blockIdx.x >> 5, g = blockIdx.x & 31;
    const float* xp = x    + ((size_t)b * CCH + g * 8) * T_LEN;
    float*       op = g_xn + ((size_t)b * CCH + g * 8) * T_LEN;
    int tid = threadIdx.x;

    float s = 0.f, s2 = 0.f;
    for (int i = tid; i < 8 * T_LEN; i += 256) {
        float v = xp[i]; s += v; s2 += v * v;
    }
    __shared__ float rs[256], rq[256];
    rs[tid] = s; rq[tid] = s2; __syncthreads();
    for (int off = 128; off; off >>= 1) {
        if (tid < off) { rs[tid] += rs[tid + off]; rq[tid] += rq[tid + off]; }
        __syncthreads();
    }
    __shared__ float sm_mean, sm_rstd;
    if (tid == 0) {
        float mean = rs[0] * (1.f / (8.f * T_LEN));
        float var  = rq[0] * (1.f / (8.f * T_LEN)) - mean * mean;
        sm_mean = mean;
        sm_rstd = rsqrtf(var + 1e-5f);
    }
    __syncthreads();
    float mean = sm_mean, rstd = sm_rstd;
    for (int i = tid; i < 8 * T_LEN; i += 256) {
        int c = g * 8 + (i >> 12);
        op[i] = (xp[i] - mean) * rstd * w[c] + bb[c];
    }
}

// ---------------- tiled SGEMM: C[M,4096] = A[M,256] @ B[256,4096] ----------
// MODE 0: B = g_xn[z],  C = g_qkv[z]                 (QKV projection)
// MODE 1: B = g_att[z], C = out[z] + bias + resid[z] (out projection)
template <int MODE>
__global__ void sgemm64(const float* __restrict__ A, int M,
                        float* __restrict__ outg,
                        const float* __restrict__ bias,
                        const float* __restrict__ residg) {
    int z = blockIdx.z;
    const float* B = (MODE == 0) ? (g_xn  + (size_t)z * CCH * T_LEN)
                                 : (g_att + (size_t)z * CCH * T_LEN);
    float* C = (MODE == 0) ? (g_qkv + (size_t)z * 3 * CCH * T_LEN)
                           : (outg  + (size_t)z * CCH * T_LEN);

    int n0 = blockIdx.x * 64, m0 = blockIdx.y * 64;
    int tid = threadIdx.x, tx = tid & 15, ty = tid >> 4;

    __shared__ float As[16][64];   // [k][m]
    __shared__ float Bs[16][64];   // [k][n]

    float acc[4][4] = {};

    int ai = tid >> 2;            // 0..63 (m within tile)
    int aj = (tid & 3) * 4;       // 0,4,8,12 (k offset)
    int bcol = tid & 63, brow0 = tid >> 6;

    for (int k0 = 0; k0 < 256; k0 += 16) {
        float4 av = *(const float4*)&A[(size_t)(m0 + ai) * 256 + k0 + aj];
        As[aj + 0][ai] = av.x; As[aj + 1][ai] = av.y;
        As[aj + 2][ai] = av.z; As[aj + 3][ai] = av.w;
#pragma unroll
        for (int r = 0; r < 4; r++) {
            int kk = brow0 + r * 4;
            Bs[kk][bcol] = B[(size_t)(k0 + kk) * T_LEN + n0 + bcol];
        }
        __syncthreads();
#pragma unroll
        for (int kk = 0; kk < 16; kk++) {
            float4 a  = *(const float4*)&As[kk][ty * 4];
            float4 bv = *(const float4*)&Bs[kk][tx * 4];
            acc[0][0] += a.x * bv.x; acc[0][1] += a.x * bv.y; acc[0][2] += a.x * bv.z; acc[0][3] += a.x * bv.w;
            acc[1][0] += a.y * bv.x; acc[1][1] += a.y * bv.y; acc[1][2] += a.y * bv.z; acc[1][3] += a.y * bv.w;
            acc[2][0] += a.z * bv.x; acc[2][1] += a.z * bv.y; acc[2][2] += a.z * bv.z; acc[2][3] += a.z * bv.w;
            acc[3][0] += a.w * bv.x; acc[3][1] += a.w * bv.y; acc[3][2] += a.w * bv.z; acc[3][3] += a.w * bv.w;
        }
        __syncthreads();
    }

#pragma unroll
    for (int ii = 0; ii < 4; ii++) {
        int m = m0 + ty * 4 + ii;
        size_t base = (size_t)m * T_LEN + n0 + tx * 4;
        float4 r = make_float4(acc[ii][0], acc[ii][1], acc[ii][2], acc[ii][3]);
        if (MODE == 1) {
            const float* resid = residg + (size_t)z * CCH * T_LEN;
            float bsv = bias[m];
            float4 x4 = *(const float4*)&resid[base];
            r.x += bsv + x4.x; r.y += bsv + x4.y;
            r.z += bsv + x4.z; r.w += bsv + x4.w;
        }
        *(float4*)&C[base] = r;
    }
}

// ---------------- flash attention (fp32, 64-query tile, online softmax) ----
// qkv layout per (b,hh): q rows [192*hh+0,64), k [+64,128), v [+128,192), T cols
// smem: Qs[64][64], Ks[64][64], Ps[64][64], Vs[64][68] (V transposed, padded)
__global__ void flash_kernel() {
    extern __shared__ float sm[];
    float* Qs = sm;             // 4096 floats  [d][t]
    float* Ks = sm + 4096;      // 4096 floats  [d][s]
    float* Ps = sm + 8192;      // 4096 floats  [i][j]
    float* Vs = sm + 12288;     // 64*68 floats [s][d] (pad 68)

    int bh = blockIdx.y;
    int b = bh >> 2, hh = bh & 3;
    int t0 = blockIdx.x * 64;
    const float* qb = g_qkv + ((size_t)b * 768 + hh * 192) * T_LEN;
    const float* kb = qb + (size_t)64  * T_LEN;
    const float* vb = qb + (size_t)128 * T_LEN;

    int tid = threadIdx.x, tx = tid & 15, ty = tid >> 4;

    // load Q tile, fold scale^2 = 1/sqrt(64) = 1/8 into Q
    for (int idx = tid; idx < 4096; idx += 256) {
        int d = idx >> 6, t = idx & 63;
        Qs[idx] = qb[(size_t)d * T_LEN + t0 + t] * 0.125f;
    }

    float m[4], l[4] = {0.f, 0.f, 0.f, 0.f};
    float o[4][4] = {};
    m[0] = m[1] = m[2] = m[3] = -1e30f;

    for (int s0 = 0; s0 < T_LEN; s0 += 64) {
        for (int idx = tid; idx < 4096; idx += 256) {
            int d = idx >> 6, s = idx & 63;
            float kvv = kb[(size_t)d * T_LEN + s0 + s];
            float vvv = vb[(size_t)d * T_LEN + s0 + s];
            Ks[idx] = kvv;
            Vs[s * 68 + d] = vvv;   // transpose for conflict-free PV reads
        }
        __syncthreads();

        // S = (Q*s)^T (K*s) : thread (tx,ty) owns rows ty*4.., cols tx*4..
        float s_[4][4] = {};
#pragma unroll 8
        for (int d = 0; d < 64; d++) {
            float4 q = *(const float4*)&Qs[d * 64 + ty * 4];
            float4 k = *(const float4*)&Ks[d * 64 + tx * 4];
            s_[0][0] += q.x * k.x; s_[0][1] += q.x * k.y; s_[0][2] += q.x * k.z; s_[0][3] += q.x * k.w;
            s_[1][0] += q.y * k.x; s_[1][1] += q.y * k.y; s_[1][2] += q.y * k.z; s_[1][3] += q.y * k.w;
            s_[2][0] += q.z * k.x; s_[2][1] += q.z * k.y; s_[2][2] += q.z * k.z; s_[2][3] += q.z * k.w;
            s_[3][0] += q.w * k.x; s_[3][1] += q.w * k.y; s_[3][2] += q.w * k.z; s_[3][3] += q.w * k.w;
        }

        // online softmax per query row (16-lane butterfly within tx group)
#pragma unroll
        for (int ii = 0; ii < 4; ii++) {
            float mx = fmaxf(fmaxf(s_[ii][0], s_[ii][1]), fmaxf(s_[ii][2], s_[ii][3]));
#pragma unroll
            for (int off = 8; off; off >>= 1)
                mx = fmaxf(mx, __shfl_xor_sync(0xffffffffu, mx, off));
            float mn = fmaxf(m[ii], mx);
            float al = __expf(m[ii] - mn);
            float p0 = __expf(s_[ii][0] - mn);
            float p1 = __expf(s_[ii][1] - mn);
            float p2 = __expf(s_[ii][2] - mn);
            float p3 = __expf(s_[ii][3] - mn);
            s_[ii][0] = p0; s_[ii][1] = p1; s_[ii][2] = p2; s_[ii][3] = p3;
            float sum = (p0 + p1) + (p2 + p3);
#pragma unroll
            for (int off = 8; off; off >>= 1)
                sum += __shfl_xor_sync(0xffffffffu, sum, off);
            l[ii] = l[ii] * al + sum;
            m[ii] = mn;
            o[ii][0] *= al; o[ii][1] *= al; o[ii][2] *= al; o[ii][3] *= al;
        }

        // publish P tile
#pragma unroll
        for (int ii = 0; ii < 4; ii++)
            *(float4*)&Ps[(ty * 4 + ii) * 64 + tx * 4] =
                make_float4(s_[ii][0], s_[ii][1], s_[ii][2], s_[ii][3]);
        __syncthreads();

        // O += P @ V^T  (thread owns O[i = ty*4.., d = tx*4..])
#pragma unroll 4
        for (int j = 0; j < 64; j += 4) {
            float4 p0 = *(const float4*)&Ps[(ty * 4 + 0) * 64 + j];
            float4 p1 = *(const float4*)&Ps[(ty * 4 + 1) * 64 + j];
            float4 p2 = *(const float4*)&Ps[(ty * 4 + 2) * 64 + j];
            float4 p3 = *(const float4*)&Ps[(ty * 4 + 3) * 64 + j];
            float4 v0 = *(const float4*)&Vs[(j + 0) * 68 + tx * 4];
            float4 v1 = *(const float4*)&Vs[(j + 1) * 68 + tx * 4];
            float4 v2 = *(const float4*)&Vs[(j + 2) * 68 + tx * 4];
            float4 v3 = *(const float4*)&Vs[(j + 3) * 68 + tx * 4];
            o[0][0] += p0.x * v0.x + p0.y * v1.x + p0.z * v2.x + p0.w * v3.x;
            o[0][1] += p0.x * v0.y + p0.y * v1.y + p0.z * v2.y + p0.w * v3.y;
            o[0][2] += p0.x * v0.z + p0.y * v1.z + p0.z * v2.z + p0.w * v3.z;
            o[0][3] += p0.x * v0.w + p0.y * v1.w + p0.z * v2.w + p0.w * v3.w;
            o[1][0] += p1.x * v0.x + p1.y * v1.x + p1.z * v2.x + p1.w * v3.x;
            o[1][1] += p1.x * v0.y + p1.y * v1.y + p1.z * v2.y + p1.w * v3.y;
            o[1][2] += p1.x * v0.z + p1.y * v1.z + p1.z * v2.z + p1.w * v3.z;
            o[1][3] += p1.x * v0.w + p1.y * v1.w + p1.z * v2.w + p1.w * v3.w;
            o[2][0] += p2.x * v0.x + p2.y * v1.x + p2.z * v2.x + p2.w * v3.x;
            o[2][1] += p2.x * v0.y + p2.y * v1.y + p2.z * v2.y + p2.w * v3.y;
            o[2][2] += p2.x * v0.z + p2.y * v1.z + p2.z * v2.z + p2.w * v3.z;
            o[2][3] += p2.x * v0.w + p2.y * v1.w + p2.z * v2.w + p2.w * v3.w;
            o[3][0] += p3.x * v0.x + p3.y * v1.x + p3.z * v2.x + p3.w * v3.x;
            o[3][1] += p3.x * v0.y + p3.y * v1.y + p3.z * v2.y + p3.w * v3.y;
            o[3][2] += p3.x * v0.z + p3.y * v1.z + p3.z * v2.z + p3.w * v3.z;
            o[3][3] += p3.x * v0.w + p3.y * v1.w + p3.z * v2.w + p3.w * v3.w;
        }
        __syncthreads();
    }

    float inv[4];
#pragma unroll
    for (int ii = 0; ii < 4; ii++) inv[ii] = 1.f / l[ii];

    // stage O as [d][i] stride 65 (reuse Qs/Ks area), then coalesced global write
    float* Os = sm;
#pragma unroll
    for (int ii = 0; ii < 4; ii++)
#pragma unroll
        for (int dd = 0; dd < 4; dd++)
            Os[(tx * 4 + dd) * 65 + ty * 4 + ii] = o[ii][dd] * inv[ii];
    __syncthreads();

    float* ab = g_att + ((size_t)b * CCH + hh * 64) * T_LEN + t0;
    for (int idx = tid; idx < 4096; idx += 256) {
        int d = idx >> 6, i = idx & 63;
        ab[(size_t)d * T_LEN + i] = Os[d * 65 + i];
    }
}

// ---------------- launch --------------------------------------------------
extern "C" void kernel_launch(void* const* d_in, const int* in_sizes, int n_in,
                              void* d_out, int out_size) {
    const float* x      = (const float*)d_in[0];
    const float* norm_w = (const float*)d_in[1];
    const float* norm_b = (const float*)d_in[2];
    const float* qkv_w  = (const float*)d_in[3];
    const float* proj_w = (const float*)d_in[4];
    const float* proj_b = (const float*)d_in[5];
    float* out = (float*)d_out;

    // 1) GroupNorm
    gn_kernel<<<64, 256>>>(x, norm_w, norm_b);

    // 2) QKV projection: [768,256] @ [256,4096] per batch
    sgemm64<0><<<dim3(64, 12, 2), 256>>>(qkv_w, 768, nullptr, nullptr, nullptr);

    // 3) flash attention: 8 batch-heads x 64 query tiles
    static const int FLASH_SMEM = 66560;
    cudaFuncSetAttribute(flash_kernel, cudaFuncAttributeMaxDynamicSharedMemorySize, FLASH_SMEM);
    flash_kernel<<<dim3(64, 8), 256, FLASH_SMEM>>>();

    // 4) output projection + bias + residual
    sgemm64<1><<<dim3(64, 4, 2), 256>>>(proj_w, 256, out, proj_b, x);
}

// round 11
// speedup vs baseline: 2.3046x; 2.3046x over previous
#include <cuda_runtime.h>
#include <cstdint>

#define T_LEN 4096
#define CCH   256
#define BATCH 2

// ---------------- scratch (device globals; no allocation allowed) ----------
__device__ float g_xn [BATCH * CCH * T_LEN];          // normalized input [B,C,T]
__device__ float g_qkv[BATCH * 3 * CCH * T_LEN];      // qkv [B,3C,T]
__device__ float g_att[BATCH * CCH * T_LEN];          // attention out [B,C,T]

// ---------------- tf32 helpers --------------------------------------------
__device__ __forceinline__ uint32_t f2tf(float x) {
    uint32_t u;
    asm("cvt.rna.tf32.f32 %0, %1;" : "=r"(u) : "f"(x));
    return u;
}

__device__ __forceinline__ void mma_tf32(float* d, const uint32_t* a,
                                         uint32_t b0, uint32_t b1) {
    asm volatile(
        "mma.sync.aligned.m16n8k8.row.col.f32.tf32.tf32.f32 "
        "{%0,%1,%2,%3}, {%4,%5,%6,%7}, {%8,%9}, {%0,%1,%2,%3};"
        : "+f"(d[0]), "+f"(d[1]), "+f"(d[2]), "+f"(d[3])
        : "r"(a[0]), "r"(a[1]), "r"(a[2]), "r"(a[3]), "r"(b0), "r"(b1));
}

// ---------------- GroupNorm (32 groups of 8 channels, over C/G x T) --------
__global__ void gn_kernel(const float* __restrict__ x,
                          const float* __restrict__ w,
                          const float* __restrict__ bb) {
    int b = blockIdx.x >> 5, g = blockIdx.x & 31;
    const float* xp = x    + ((size_t)b * CCH + g * 8) * T_LEN;
    float*       op = g_xn + ((size_t)b * CCH + g * 8) * T_LEN;
    int tid = threadIdx.x;

    float s = 0.f, s2 = 0.f;
    for (int i = tid; i < 8 * T_LEN; i += 256) {
        float v = xp[i]; s += v; s2 += v * v;
    }
    __shared__ float rs[256], rq[256];
    rs[tid] = s; rq[tid] = s2; __syncthreads();
    for (int off = 128; off; off >>= 1) {
        if (tid < off) { rs[tid] += rs[tid + off]; rq[tid] += rq[tid + off]; }
        __syncthreads();
    }
    __shared__ float sm_mean, sm_rstd;
    if (tid == 0) {
        float mean = rs[0] * (1.f / (8.f * T_LEN));
        float var  = rq[0] * (1.f / (8.f * T_LEN)) - mean * mean;
        sm_mean = mean;
        sm_rstd = rsqrtf(var + 1e-5f);
    }
    __syncthreads();
    float mean = sm_mean, rstd = sm_rstd;
    for (int i = tid; i < 8 * T_LEN; i += 256) {
        int c = g * 8 + (i >> 12);
        op[i] = (xp[i] - mean) * rstd * w[c] + bb[c];
    }
}

// ---------------- QKV projection on tensor cores (tf32) --------------------
// C[768,4096] = qkv_w[768,256] @ g_xn[256,4096] per batch.
// Block: 256 thr = 8 warps; tile 128m x 64n; k staged 16 wide.
// As[m][k] stride 20, Bs[n][k] stride 20 (transposed at staging, tf32-rounded).
__global__ void qkv_mma_kernel(const float* __restrict__ Aw) {
    int z = blockIdx.z;
    const float* B = g_xn  + (size_t)z * CCH * T_LEN;
    float*       C = g_qkv + (size_t)z * 3 * CCH * T_LEN;
    int n0 = blockIdx.x * 64, m0 = blockIdx.y * 128;

    __shared__ float As[128 * 20];
    __shared__ float Bs[64 * 20];

    int tid = threadIdx.x, warp = tid >> 5, lane = tid & 31;
    int gq = lane >> 2, tg = lane & 3;

    float o[8][4] = {};

    for (int k0 = 0; k0 < 256; k0 += 16) {
        // stage A: 128x16, each thread one half-row (8 floats)
        {
            int mi = tid >> 1, j = (tid & 1) * 8;
            const float* src = &Aw[(size_t)(m0 + mi) * 256 + k0 + j];
            float4 v0 = *(const float4*)&src[0];
            float4 v1 = *(const float4*)&src[4];
            float* ap = &As[mi * 20 + j];
            ap[0] = __uint_as_float(f2tf(v0.x));
            ap[1] = __uint_as_float(f2tf(v0.y));
            ap[2] = __uint_as_float(f2tf(v0.z));
            ap[3] = __uint_as_float(f2tf(v0.w));
            ap[4] = __uint_as_float(f2tf(v1.x));
            ap[5] = __uint_as_float(f2tf(v1.y));
            ap[6] = __uint_as_float(f2tf(v1.z));
            ap[7] = __uint_as_float(f2tf(v1.w));
        }
        // stage B: 16k x 64n, transposed into Bs[n][k]
#pragma unroll
        for (int r = 0; r < 4; r++) {
            int idx = tid + r * 256;
            int k = idx >> 6, n = idx & 63;
            Bs[n * 20 + k] =
                __uint_as_float(f2tf(B[(size_t)(k0 + k) * T_LEN + n0 + n]));
        }
        __syncthreads();

#pragma unroll
        for (int kk = 0; kk < 2; kk++) {
            uint32_t a[4];
            const float* arow = &As[(warp * 16 + gq) * 20 + kk * 8 + tg];
            a[0] = __float_as_uint(arow[0]);
            a[1] = __float_as_uint(arow[8 * 20]);
            a[2] = __float_as_uint(arow[4]);
            a[3] = __float_as_uint(arow[8 * 20 + 4]);
#pragma unroll
            for (int nb = 0; nb < 8; nb++) {
                const float* bp = &Bs[(nb * 8 + gq) * 20 + kk * 8 + tg];
                mma_tf32(o[nb], a, __float_as_uint(bp[0]), __float_as_uint(bp[4]));
            }
        }
        __syncthreads();
    }

    int m = m0 + warp * 16 + gq;
#pragma unroll
    for (int nb = 0; nb < 8; nb++) {
        int col = n0 + nb * 8 + 2 * tg;
        *(float2*)&C[(size_t)m * T_LEN + col]       = make_float2(o[nb][0], o[nb][1]);
        *(float2*)&C[(size_t)(m + 8) * T_LEN + col] = make_float2(o[nb][2], o[nb][3]);
    }
}

// ---------------- tiled SGEMM (fp32) for proj + bias + residual ------------
__global__ void sgemm_proj(const float* __restrict__ A,
                           float* __restrict__ outg,
                           const float* __restrict__ bias,
                           const float* __restrict__ residg) {
    int z = blockIdx.z;
    const float* B = g_att + (size_t)z * CCH * T_LEN;
    float* C = outg + (size_t)z * CCH * T_LEN;

    int n0 = blockIdx.x * 64, m0 = blockIdx.y * 64;
    int tid = threadIdx.x, tx = tid & 15, ty = tid >> 4;

    __shared__ float As[16][64];
    __shared__ float Bs[16][64];

    float acc[4][4] = {};

    int ai = tid >> 2;
    int aj = (tid & 3) * 4;
    int bcol = tid & 63, brow0 = tid >> 6;

    for (int k0 = 0; k0 < 256; k0 += 16) {
        float4 av = *(const float4*)&A[(size_t)(m0 + ai) * 256 + k0 + aj];
        As[aj + 0][ai] = av.x; As[aj + 1][ai] = av.y;
        As[aj + 2][ai] = av.z; As[aj + 3][ai] = av.w;
#pragma unroll
        for (int r = 0; r < 4; r++) {
            int kk = brow0 + r * 4;
            Bs[kk][bcol] = B[(size_t)(k0 + kk) * T_LEN + n0 + bcol];
        }
        __syncthreads();
#pragma unroll
        for (int kk = 0; kk < 16; kk++) {
            float4 a  = *(const float4*)&As[kk][ty * 4];
            float4 bv = *(const float4*)&Bs[kk][tx * 4];
            acc[0][0] += a.x * bv.x; acc[0][1] += a.x * bv.y; acc[0][2] += a.x * bv.z; acc[0][3] += a.x * bv.w;
            acc[1][0] += a.y * bv.x; acc[1][1] += a.y * bv.y; acc[1][2] += a.y * bv.z; acc[1][3] += a.y * bv.w;
            acc[2][0] += a.z * bv.x; acc[2][1] += a.z * bv.y; acc[2][2] += a.z * bv.z; acc[2][3] += a.z * bv.w;
            acc[3][0] += a.w * bv.x; acc[3][1] += a.w * bv.y; acc[3][2] += a.w * bv.z; acc[3][3] += a.w * bv.w;
        }
        __syncthreads();
    }

#pragma unroll
    for (int ii = 0; ii < 4; ii++) {
        int m = m0 + ty * 4 + ii;
        size_t base = (size_t)m * T_LEN + n0 + tx * 4;
        const float* resid = residg + (size_t)z * CCH * T_LEN;
        float bsv = bias[m];
        float4 x4 = *(const float4*)&resid[base];
        float4 r = make_float4(acc[ii][0] + bsv + x4.x, acc[ii][1] + bsv + x4.y,
                               acc[ii][2] + bsv + x4.z, acc[ii][3] + bsv + x4.w);
        *(float4*)&C[base] = r;
    }
}

// ---------------- flash attention: tf32 tensor-core version ---------------
// Block: 128 queries (8 warps x 16 rows), KV tile 64, d=64.
// smem: Ks[64][68] ([s][d], tf32), Vs[64][68] ([d][s], tf32), Ps[128][68]
__global__ void flash_mma_kernel() {
    extern __shared__ float sm[];
    float* Ks = sm;                   // 64*68
    float* Vs = sm + 64 * 68;         // 64*68
    float* Ps = sm + 2 * 64 * 68;     // 128*68 (per-warp 16-row slices)

    int bh = blockIdx.y;
    int b = bh >> 2, hh = bh & 3;
    int t0 = blockIdx.x * 128;
    const float* qb = g_qkv + ((size_t)b * 768 + hh * 192) * T_LEN;
    const float* kb = qb + (size_t)64  * T_LEN;
    const float* vb = qb + (size_t)128 * T_LEN;

    int tid = threadIdx.x;
    int warp = tid >> 5, lane = tid & 31;
    int gq = lane >> 2, tg = lane & 3;     // groupID, threadInGroup
    int qrow0 = t0 + warp * 16 + gq;       // global q index of A-row "gq"

    // Q fragments (scale 1/8 folded in), tf32-rounded, register-resident
    uint32_t qa[8][4];
#pragma unroll
    for (int kk = 0; kk < 8; kk++) {
        int d0 = kk * 8 + tg;
        qa[kk][0] = f2tf(qb[(size_t)(d0)     * T_LEN + qrow0]     * 0.125f);
        qa[kk][1] = f2tf(qb[(size_t)(d0)     * T_LEN + qrow0 + 8] * 0.125f);
        qa[kk][2] = f2tf(qb[(size_t)(d0 + 4) * T_LEN + qrow0]     * 0.125f);
        qa[kk][3] = f2tf(qb[(size_t)(d0 + 4) * T_LEN + qrow0 + 8] * 0.125f);
    }

    float o[8][4] = {};
    float m0 = -1e30f, m1 = -1e30f, l0 = 0.f, l1 = 0.f;

    float* Pw = Ps + warp * 16 * 68;   // this warp's P slice

    for (int s0 = 0; s0 < T_LEN; s0 += 64) {
        // stage K [s][68] and V [d][68] (tf32-rounded once here)
        for (int idx = tid; idx < 4096; idx += 256) {
            int d = idx >> 6, s = idx & 63;
            float kv = kb[(size_t)d * T_LEN + s0 + s];
            float vv = vb[(size_t)d * T_LEN + s0 + s];
            Ks[s * 68 + d] = __uint_as_float(f2tf(kv));
            Vs[d * 68 + s] = __uint_as_float(f2tf(vv));
        }
        __syncthreads();

        // S = Q K^T : per warp 16x64, acc fragments s_[nb][4]
        float s_[8][4] = {};
#pragma unroll
        for (int kk = 0; kk < 8; kk++) {
#pragma unroll
            for (int nb = 0; nb < 8; nb++) {
                const float* kp = &Ks[(nb * 8 + gq) * 68 + kk * 8 + tg];
                uint32_t b0 = __float_as_uint(kp[0]);
                uint32_t b1 = __float_as_uint(kp[4]);
                mma_tf32(s_[nb], qa[kk], b0, b1);
            }
        }

        // online softmax: half 0 = rows gq (c0,c1), half 1 = rows gq+8 (c2,c3)
        float mx0 = -1e30f, mx1 = -1e30f;
#pragma unroll
        for (int nb = 0; nb < 8; nb++) {
            mx0 = fmaxf(mx0, fmaxf(s_[nb][0], s_[nb][1]));
            mx1 = fmaxf(mx1, fmaxf(s_[nb][2], s_[nb][3]));
        }
        mx0 = fmaxf(mx0, __shfl_xor_sync(0xffffffffu, mx0, 1));
        mx0 = fmaxf(mx0, __shfl_xor_sync(0xffffffffu, mx0, 2));
        mx1 = fmaxf(mx1, __shfl_xor_sync(0xffffffffu, mx1, 1));
        mx1 = fmaxf(mx1, __shfl_xor_sync(0xffffffffu, mx1, 2));
        float mn0 = fmaxf(m0, mx0), mn1 = fmaxf(m1, mx1);
        float al0 = __expf(m0 - mn0), al1 = __expf(m1 - mn1);
        m0 = mn0; m1 = mn1;

        float sum0 = 0.f, sum1 = 0.f;
#pragma unroll
        for (int nb = 0; nb < 8; nb++) {
            float p00 = __expf(s_[nb][0] - mn0);
            float p01 = __expf(s_[nb][1] - mn0);
            float p10 = __expf(s_[nb][2] - mn1);
            float p11 = __expf(s_[nb][3] - mn1);
            sum0 += p00 + p01;
            sum1 += p10 + p11;
            int col = nb * 8 + 2 * tg;
            *(float2*)&Pw[gq * 68 + col] =
                make_float2(__uint_as_float(f2tf(p00)), __uint_as_float(f2tf(p01)));
            *(float2*)&Pw[(gq + 8) * 68 + col] =
                make_float2(__uint_as_float(f2tf(p10)), __uint_as_float(f2tf(p11)));
        }
        sum0 += __shfl_xor_sync(0xffffffffu, sum0, 1);
        sum0 += __shfl_xor_sync(0xffffffffu, sum0, 2);
        sum1 += __shfl_xor_sync(0xffffffffu, sum1, 1);
        sum1 += __shfl_xor_sync(0xffffffffu, sum1, 2);
        l0 = l0 * al0 + sum0;
        l1 = l1 * al1 + sum1;

#pragma unroll
        for (int nb = 0; nb < 8; nb++) {
            o[nb][0] *= al0; o[nb][1] *= al0;
            o[nb][2] *= al1; o[nb][3] *= al1;
        }
        __syncwarp();   // P store -> P load, warp-private

        // O += P V : A from Pw, B from Vs[d][s]
#pragma unroll
        for (int kk = 0; kk < 8; kk++) {
            uint32_t pa[4];
            pa[0] = __float_as_uint(Pw[(gq)     * 68 + kk * 8 + tg]);
            pa[1] = __float_as_uint(Pw[(gq + 8) * 68 + kk * 8 + tg]);
            pa[2] = __float_as_uint(Pw[(gq)     * 68 + kk * 8 + tg + 4]);
            pa[3] = __float_as_uint(Pw[(gq + 8) * 68 + kk * 8 + tg + 4]);
#pragma unroll
            for (int nb = 0; nb < 8; nb++) {
                const float* vp = &Vs[(nb * 8 + gq) * 68 + kk * 8 + tg];
                uint32_t b0 = __float_as_uint(vp[0]);
                uint32_t b1 = __float_as_uint(vp[4]);
                mma_tf32(o[nb], pa, b0, b1);
            }
        }
        __syncthreads();   // protect Ks/Vs before next staging
    }

    float inv0 = 1.f / l0, inv1 = 1.f / l1;
    float* ab = g_att + ((size_t)b * CCH + hh * 64) * T_LEN;
#pragma unroll
    for (int nb = 0; nb < 8; nb++) {
        int d = nb * 8 + 2 * tg;
        ab[(size_t)(d)     * T_LEN + qrow0]     = o[nb][0] * inv0;
        ab[(size_t)(d + 1) * T_LEN + qrow0]     = o[nb][1] * inv0;
        ab[(size_t)(d)     * T_LEN + qrow0 + 8] = o[nb][2] * inv1;
        ab[(size_t)(d + 1) * T_LEN + qrow0 + 8] = o[nb][3] * inv1;
    }
}

// ---------------- launch --------------------------------------------------
extern "C" void kernel_launch(void* const* d_in, const int* in_sizes, int n_in,
                              void* d_out, int out_size) {
    const float* x      = (const float*)d_in[0];
    const float* norm_w = (const float*)d_in[1];
    const float* norm_b = (const float*)d_in[2];
    const float* qkv_w  = (const float*)d_in[3];
    const float* proj_w = (const float*)d_in[4];
    const float* proj_b = (const float*)d_in[5];
    float* out = (float*)d_out;

    // 1) GroupNorm
    gn_kernel<<<64, 256>>>(x, norm_w, norm_b);

    // 2) QKV projection (tf32 mma): [768,256] @ [256,4096] per batch
    qkv_mma_kernel<<<dim3(64, 6, 2), 256>>>(qkv_w);

    // 3) flash attention (tf32 mma): 32 q-tiles x 8 batch-heads
    static const int FLASH_SMEM = (2 * 64 * 68 + 128 * 68) * 4;  // 69632 B
    cudaFuncSetAttribute(flash_mma_kernel, cudaFuncAttributeMaxDynamicSharedMemorySize, FLASH_SMEM);
    flash_mma_kernel<<<dim3(32, 8), 256, FLASH_SMEM>>>();

    // 4) output projection + bias + residual (fp32)
    sgemm_proj<<<dim3(64, 4, 2), 256>>>(proj_w, out, proj_b, x);
}